// round 1
// baseline (speedup 1.0000x reference)
#include <cuda_runtime.h>
#include <math.h>

// ---------------------------------------------------------------------------
// DensityNet: two edge-based RBF convolutions (hat basis on polar coords)
// with scatter-add into per-fluid-particle outputs.
//
// Inputs (metadata order):
//  0 fluidPositions    [Nf,2] f32
//  1 boundaryPositions [Nb,2] f32
//  2 fluidFeatures     [Nf,1] f32
//  3 boundaryFeatures  [Nb,1] f32
//  4 Wf                [8,8,1,1] f32
//  5 Wb                [8,8,1,1] f32
//  6 support           scalar f32 (1 element)
//  7 fi                [Ef] i32
//  8 fj                [Ef] i32
//  9 bf                [Eb] i32
// 10 bb                [Eb] i32
// Output: [Nf] f32
// ---------------------------------------------------------------------------

#define NRBF 8
#define HAT_WIDTH (2.0f / (NRBF - 1))   // 2/7
#define INV_HAT_WIDTH ((NRBF - 1) * 0.5f) // 3.5

__global__ void zero_kernel(float* out, int n) {
    int i = blockIdx.x * blockDim.x + threadIdx.x;
    if (i < n) out[i] = 0.0f;
}

// 2-tap hat basis: returns left index i (0..K-2) and weights (1-f, f).
__device__ __forceinline__ void hat2(float x, int& i0, float& w0, float& w1) {
    float p = (x + 1.0f) * INV_HAT_WIDTH;   // in [0, 7]
    int i = (int)floorf(p);
    i = max(0, min(i, NRBF - 2));
    float f = p - (float)i;
    // clamp for tiny fp overshoot (r slightly > 1 after clip)
    f = fminf(fmaxf(f, 0.0f), 1.0f);
    i0 = i;
    w0 = 1.0f - f;
    w1 = f;
}

__global__ void edge_conv_kernel(
    const float2* __restrict__ posQ,    // query positions (fluid)
    const float2* __restrict__ posS,    // source positions
    const float* __restrict__ featS,    // source features [Ns]
    const int*   __restrict__ ei,       // edge -> query index
    const int*   __restrict__ ej,       // edge -> source index
    const float* __restrict__ W,        // [8,8]
    const float* __restrict__ support_ptr,
    int E,
    float* __restrict__ out)
{
    const float inv_support = 1.0f / support_ptr[0];
    int e = blockIdx.x * blockDim.x + threadIdx.x;
    if (e >= E) return;

    int qi = ei[e];
    int sj = ej[e];

    float2 pq = posQ[qi];
    float2 ps = posS[sj];

    float dx = (ps.x - pq.x) * inv_support;
    float dy = (ps.y - pq.y) * inv_support;
    dx = fminf(fmaxf(dx, -1.0f), 1.0f);
    dy = fminf(fmaxf(dy, -1.0f), 1.0f);

    float d2 = dx * dx + dy * dy;
    bool small = d2 < 1e-12f;

    float r = small ? 0.0f : sqrtf(d2);
    float ddx = small ? 1.0f : dx;
    float ddy = small ? 0.0f : dy;
    float theta = atan2f(ddy, ddx);

    float u = 2.0f * r - 1.0f;
    float v = theta * (float)(1.0 / M_PI);

    int ia, ib;
    float a0, a1, b0, b1;
    hat2(u, ia, a0, a1);
    hat2(v, ib, b0, b1);

    float omr = 1.0f - r;
    float omr2 = omr * omr;
    float win = fmaxf(omr2 * omr2 * (1.0f + 4.0f * r), 0.0f);

    float xj = __ldg(&featS[sj]);

    const float* Wr0 = W + ia * NRBF + ib;
    const float* Wr1 = Wr0 + NRBF;
    float w = a0 * (b0 * __ldg(Wr0) + b1 * __ldg(Wr0 + 1))
            + a1 * (b0 * __ldg(Wr1) + b1 * __ldg(Wr1 + 1));

    atomicAdd(&out[qi], w * win * xj);
}

extern "C" void kernel_launch(void* const* d_in, const int* in_sizes, int n_in,
                              void* d_out, int out_size) {
    const float2* fluidPos    = (const float2*)d_in[0];
    const float2* boundaryPos = (const float2*)d_in[1];
    const float*  fluidFeat   = (const float*)d_in[2];
    const float*  boundFeat   = (const float*)d_in[3];
    const float*  Wf          = (const float*)d_in[4];
    const float*  Wb          = (const float*)d_in[5];
    const float*  support     = (const float*)d_in[6];
    const int*    fi          = (const int*)d_in[7];
    const int*    fj          = (const int*)d_in[8];
    const int*    bf          = (const int*)d_in[9];
    const int*    bb          = (const int*)d_in[10];

    float* out = (float*)d_out;
    int Ef = in_sizes[7];
    int Eb = in_sizes[9];

    // zero the output
    {
        int threads = 256;
        int blocks = (out_size + threads - 1) / threads;
        zero_kernel<<<blocks, threads>>>(out, out_size);
    }

    // fluid-fluid convolution
    if (Ef > 0) {
        int threads = 256;
        int blocks = (Ef + threads - 1) / threads;
        edge_conv_kernel<<<blocks, threads>>>(
            fluidPos, fluidPos, fluidFeat, fi, fj, Wf, support, Ef, out);
    }

    // fluid-boundary convolution
    if (Eb > 0) {
        int threads = 256;
        int blocks = (Eb + threads - 1) / threads;
        edge_conv_kernel<<<blocks, threads>>>(
            fluidPos, boundaryPos, boundFeat, bf, bb, Wb, support, Eb, out);
    }
}

// round 2
// speedup vs baseline: 1.2825x; 1.2825x over previous
#include <cuda_runtime.h>
#include <math.h>

// ---------------------------------------------------------------------------
// DensityNet: fused dual RBF edge convolution with warp-segmented reduction.
//
// Inputs (metadata order):
//  0 fluidPositions [Nf,2]  1 boundaryPositions [Nb,2]
//  2 fluidFeatures  [Nf]    3 boundaryFeatures  [Nb]
//  4 Wf [8,8]               5 Wb [8,8]
//  6 support (1 elem)       7 fi  8 fj  9 bf  10 bb
// Output: [Nf] f32
// ---------------------------------------------------------------------------

#define NRBF 8
#define INV_HAT_WIDTH 3.5f   // (NRBF-1)/2

__global__ void zero_kernel4(float4* out, int n4) {
    int i = blockIdx.x * blockDim.x + threadIdx.x;
    if (i < n4) out[i] = make_float4(0.f, 0.f, 0.f, 0.f);
}

// 2-tap hat basis
__device__ __forceinline__ void hat2(float x, int& i0, float& w0, float& w1) {
    float p = (x + 1.0f) * INV_HAT_WIDTH;   // [0, 7]
    int i = (int)p;
    i = max(0, min(i, NRBF - 2));
    float f = p - (float)i;
    f = fminf(fmaxf(f, 0.0f), 1.0f);
    i0 = i; w0 = 1.0f - f; w1 = f;
}

// atan2(y,x)/pi via octant reduction + degree-9 odd minimax poly (err ~3e-6)
__device__ __forceinline__ float atan2_over_pi(float y, float x) {
    float ax = fabsf(x), ay = fabsf(y);
    float mn = fminf(ax, ay), mx = fmaxf(ax, ay);
    float t  = __fdividef(mn, mx);
    float t2 = t * t;
    float p = 0.00663147f;
    p = fmaf(p, t2, -0.0270968f);
    p = fmaf(p, t2,  0.0573382f);
    p = fmaf(p, t2, -0.1051301f);
    p = fmaf(p, t2,  0.3182684f);
    float a = t * p;                       // atan(t)/pi in [0, 0.25]
    float v = (ay > ax) ? (0.5f - a) : a;  // octant
    if (x < 0.0f) v = 1.0f - v;            // quadrant
    return copysignf(v, y);                // sign of y (handles +/-0 like atan2)
}

__global__ void fused_edge_kernel(
    const float2* __restrict__ fluidPos,
    const float2* __restrict__ boundaryPos,
    const float*  __restrict__ fluidFeat,
    const float*  __restrict__ boundFeat,
    const int*    __restrict__ fi, const int* __restrict__ fj,
    const int*    __restrict__ bf, const int* __restrict__ bb,
    const float*  __restrict__ Wf, const float* __restrict__ Wb,
    const float*  __restrict__ support_ptr,
    int Ef, int Etot,
    float* __restrict__ out)
{
    const unsigned FULL = 0xffffffffu;
    const int e = blockIdx.x * blockDim.x + threadIdx.x;
    const int lane = threadIdx.x & 31;

    float val = 0.0f;
    int qi = -1;

    if (e < Etot) {
        const bool isF = (e < Ef);
        const int ee = isF ? e : (e - Ef);
        const int*    EI = isF ? fi : bf;
        const int*    EJ = isF ? fj : bb;
        const float2* PS = isF ? fluidPos : boundaryPos;
        const float*  FS = isF ? fluidFeat : boundFeat;
        const float*  WW = isF ? Wf : Wb;

        qi = EI[ee];
        const int sj = EJ[ee];

        const float inv_support = __fdividef(1.0f, support_ptr[0]);
        const float2 pq = fluidPos[qi];
        const float2 ps = PS[sj];

        float dx = (ps.x - pq.x) * inv_support;
        float dy = (ps.y - pq.y) * inv_support;
        dx = fminf(fmaxf(dx, -1.0f), 1.0f);
        dy = fminf(fmaxf(dy, -1.0f), 1.0f);

        const float d2 = fmaf(dx, dx, dy * dy);
        const bool small = d2 < 1e-12f;

        const float r   = small ? 0.0f : d2 * rsqrtf(d2);
        const float ddx = small ? 1.0f : dx;
        const float ddy = small ? 0.0f : dy;

        const float u = 2.0f * r - 1.0f;
        const float v = atan2_over_pi(ddy, ddx);

        int ia, ib;
        float a0, a1, b0, b1;
        hat2(u, ia, a0, a1);
        hat2(v, ib, b0, b1);

        const float omr  = 1.0f - r;
        const float omr2 = omr * omr;
        const float win  = fmaxf(omr2 * omr2 * fmaf(4.0f, r, 1.0f), 0.0f);

        const float xj = __ldg(&FS[sj]);

        const float* Wr0 = WW + ia * NRBF + ib;
        const float* Wr1 = Wr0 + NRBF;
        const float w = a0 * fmaf(b1, __ldg(Wr0 + 1), b0 * __ldg(Wr0))
                      + a1 * fmaf(b1, __ldg(Wr1 + 1), b0 * __ldg(Wr1));

        val = w * win * xj;
    }

    // warp-segmented reduction over runs of equal qi (edges are run-sorted)
    #pragma unroll
    for (int off = 1; off < 32; off <<= 1) {
        float ov = __shfl_down_sync(FULL, val, off);
        int   oq = __shfl_down_sync(FULL, qi, off);
        if ((lane + off) < 32 && oq == qi) val += ov;
    }
    const int upq = __shfl_up_sync(FULL, qi, 1);
    const bool head = (lane == 0) || (upq != qi);
    if (head && qi >= 0) atomicAdd(&out[qi], val);
}

extern "C" void kernel_launch(void* const* d_in, const int* in_sizes, int n_in,
                              void* d_out, int out_size) {
    const float2* fluidPos    = (const float2*)d_in[0];
    const float2* boundaryPos = (const float2*)d_in[1];
    const float*  fluidFeat   = (const float*)d_in[2];
    const float*  boundFeat   = (const float*)d_in[3];
    const float*  Wf          = (const float*)d_in[4];
    const float*  Wb          = (const float*)d_in[5];
    const float*  support     = (const float*)d_in[6];
    const int*    fi          = (const int*)d_in[7];
    const int*    fj          = (const int*)d_in[8];
    const int*    bf          = (const int*)d_in[9];
    const int*    bb          = (const int*)d_in[10];

    float* out = (float*)d_out;
    const int Ef = in_sizes[7];
    const int Eb = in_sizes[9];
    const int Etot = Ef + Eb;

    // zero the output (out_size is 65536, divisible by 4)
    {
        int n4 = out_size / 4;
        int threads = 256;
        int blocks = (n4 + threads - 1) / threads;
        zero_kernel4<<<blocks, threads>>>((float4*)out, n4);
    }

    if (Etot > 0) {
        int threads = 256;
        int blocks = (Etot + threads - 1) / threads;
        fused_edge_kernel<<<blocks, threads>>>(
            fluidPos, boundaryPos, fluidFeat, boundFeat,
            fi, fj, bf, bb, Wf, Wb, support, Ef, Etot, out);
    }
}